// round 12
// baseline (speedup 1.0000x reference)
#include <cuda_runtime.h>

#define GRID 128
#define TPB  256
#define NWP  8
#define BN   32
#define TN   32
#define VISD 1024
#define FFD  512
#define OSTR (33*FFD)
#define NSLOT 52
#define SMEM_BYTES (NSLOT*128*16)

// ---------------- static device scratch (no runtime allocations) -----------
__device__ float g_pooled[BN*TN*VISD];
__device__ float g_obs_enc[BN*TN*FFD];
__device__ float g_obs_pre[TN*BN*FFD];
__device__ float g_act_pre[TN*BN*FFD];
__device__ float g_s[BN*FFD];
__device__ float g_h[2][BN*FFD];
__device__ float g_gi[BN*FFD];
__device__ float g_mid[BN*FFD];
__device__ unsigned g_arrive;

// ---------------- grid barrier (monotonic counter) -------------------------
__device__ __forceinline__ void gbar(unsigned& nbar) {
    nbar += GRID;
    __threadfence();               // release my stores (CCTL.IVALL)
    __syncthreads();
    if (threadIdx.x == 0) {
        atomicAdd(&g_arrive, 1u);
        while (*(volatile unsigned*)&g_arrive < nbar) __nanosleep(32);
        __threadfence();           // acquire: invalidate this SM's L1
    }
    __syncthreads();
}

// ---------------- math -----------------------------------------------------
__device__ __forceinline__ float sigm_f(float x) {
    return __fdividef(1.f, 1.f + __expf(-x));
}
__device__ __forceinline__ float tanh_f(float x) {
    x = fminf(fmaxf(x, -15.f), 15.f);
    float e = __expf(2.f * x);
    return (e - 1.f) * __fdividef(1.f, e + 1.f);
}
__device__ __forceinline__ float softplus_f(float x) {
    return fmaxf(x, 0.f) + __logf(1.f + __expf(-fabsf(x)));
}

// ---------------- warp GEMM tiles (lanes along K=512) ----------------------
__device__ __forceinline__ float dot16(const float4 a[4], const float4 b[4]) {
    float s = 0.f;
#pragma unroll
    for (int j = 0; j < 4; ++j)
        s += a[j].x*b[j].x + a[j].y*b[j].y + a[j].z*b[j].z + a[j].w*b[j].w;
    return s;
}
template<bool RELU>
__device__ __forceinline__ void load_act4(const float* act, int as, int lane,
                                          float4 a[4][4]) {
#pragma unroll
    for (int r = 0; r < 4; ++r) {
        const float4* p = reinterpret_cast<const float4*>(act + r*as) + lane*4;
#pragma unroll
        for (int j = 0; j < 4; ++j) {
            float4 v = p[j];
            if (RELU) { v.x=fmaxf(v.x,0.f); v.y=fmaxf(v.y,0.f);
                        v.z=fmaxf(v.z,0.f); v.w=fmaxf(v.w,0.f); }
            a[r][j] = v;
        }
    }
}
// gmem-weight variant: 4 rows x 4 cols, weight col stride ws (floats)
template<bool RELU>
__device__ __forceinline__ void mm4x4g(const float* act, int as, const float* W,
                                       int ws, int lane, float* acc) {
    float4 a[4][4];
    load_act4<RELU>(act, as, lane, a);
#pragma unroll
    for (int c = 0; c < 4; ++c) {
        float4 wv[4];
        const float4* p = reinterpret_cast<const float4*>(W + c*ws) + lane*4;
#pragma unroll
        for (int j = 0; j < 4; ++j) wv[j] = p[j];
#pragma unroll
        for (int r = 0; r < 4; ++r) acc[r*4+c] += dot16(a[r], wv);
    }
}
// smem-weight variant: cols are consecutive 128-f4 slots, swizzled offsets
template<bool RELU>
__device__ __forceinline__ void mm4x4s(const float* act, int as, const float4* sWc,
                                       const int sofs[4], int lane, float* acc) {
    float4 a[4][4];
    load_act4<RELU>(act, as, lane, a);
#pragma unroll
    for (int c = 0; c < 4; ++c) {
        float4 wv[4];
#pragma unroll
        for (int j = 0; j < 4; ++j) wv[j] = sWc[c*128 + sofs[j]];
#pragma unroll
        for (int r = 0; r < 4; ++r) acc[r*4+c] += dot16(a[r], wv);
    }
}
template<int N>
__device__ __forceinline__ void reduceN(float* acc) {
#pragma unroll
    for (int off = 16; off > 0; off >>= 1)
#pragma unroll
        for (int i = 0; i < N; ++i)
            acc[i] += __shfl_xor_sync(0xFFFFFFFFu, acc[i], off);
}

// ---------------------------------------------------------------------------
__global__ void reset_kernel() { g_arrive = 0; }

__global__ void __launch_bounds__(TPB, 1)
rssm_kernel(const float* __restrict__ img_feat, const float* __restrict__ actions,
            const float* __restrict__ eps0,     const float* __restrict__ eps_seq,
            const float* __restrict__ init_hidden,
            const float* __restrict__ W_obs,   const float* __restrict__ b_obs,
            const float* __restrict__ W_post1, const float* __restrict__ b_post1,
            const float* __restrict__ W_pm,    const float* __restrict__ b_pm,
            const float* __restrict__ W_ps,    const float* __restrict__ b_ps,
            const float* __restrict__ W_gi,    const float* __restrict__ b_gi,
            const float* __restrict__ Wih,     const float* __restrict__ Whh,
            const float* __restrict__ bih,     const float* __restrict__ bhh,
            const float* __restrict__ W_pr1,   const float* __restrict__ b_pr1,
            const float* __restrict__ W_prm,   const float* __restrict__ b_prm,
            const float* __restrict__ W_prs,   const float* __restrict__ b_prs,
            float* __restrict__ out)
{
    extern __shared__ float4 sW[];           // 52 slots x 128 float4 (swizzled)
    const int tid  = threadIdx.x;
    const int cta  = blockIdx.x;
    const int lane = tid & 31;
    const int w    = tid >> 5;
    const int gtid = cta * TPB + tid;
    const int r0   = 4 * w;                  // warp's 4 batch rows
    const int c0   = cta * 4;                // CTA's 4 feature columns
    unsigned nbar = 0;

    int sofs[4];                             // per-lane swizzled f4 offsets
#pragma unroll
    for (int j = 0; j < 4; ++j) { int ix = 4*lane + j; sofs[j] = ix ^ ((ix>>3)&7); }

    // ===== stage this CTA's scan weights into swizzled SMEM ================
    {
        const float* src[NSLOT];
#pragma unroll
        for (int j = 0; j < 4; ++j) {
            src[0+j]  = W_gi + (c0+j)*520;                       // state half
#pragma unroll
            for (int g = 0; g < 3; ++g) {
                src[4+g*4+j]  = Wih + (g*FFD + c0 + j)*FFD;
                src[16+g*4+j] = Whh + (g*FFD + c0 + j)*FFD;
            }
            src[28+j] = W_post1 + (c0+j)*1024;                   // belief half
            src[32+j] = W_pr1 + (c0+j)*FFD;
            src[36+j] = W_pm  + (c0+j)*FFD;
            src[40+j] = W_ps  + (c0+j)*FFD;
            src[44+j] = W_prm + (c0+j)*FFD;
            src[48+j] = W_prs + (c0+j)*FFD;
        }
        for (int i = tid; i < NSLOT*128; i += TPB) {
            int s = i >> 7, k = i & 127;
            sW[s*128 + (k ^ ((k>>3)&7))] =
                reinterpret_cast<const float4*>(src[s])[k];
        }
    }
    __syncthreads();

    // ===== P1: spatial mean pool over 48 floats per (b,t,v) ================
    {
        const int q = lane & 3, o = lane >> 2;
        const int warp_id = cta * NWP + w;
        const float4* base = reinterpret_cast<const float4*>(img_feat);
#pragma unroll 2
        for (int it = 0; it < 128; ++it) {
            int ob = (it * (GRID*NWP) + warp_id) * 8;
            const float4* srcp = base + (long)ob * 12;
            int fi = 12*o + q;
            float4 v0 = srcp[fi], v1 = srcp[fi+4], v2 = srcp[fi+8];
            float s = (v0.x+v0.y)+(v0.z+v0.w)+(v1.x+v1.y)+(v1.z+v1.w)
                    + (v2.x+v2.y)+(v2.z+v2.w);
            s += __shfl_xor_sync(0xFFFFFFFFu, s, 1);
            s += __shfl_xor_sync(0xFFFFFFFFu, s, 2);
            if (q == 0) g_pooled[ob + o] = s * (1.f/48.f);
        }
    }
    gbar(nbar);

    // ===== P2: obs_enc = pooled @ W_obs^T + b_obs ; act_pre ; h0 ===========
    {
        for (int rg = w; rg < 256; rg += NWP) {
            int rr0 = rg * 4;
            float acc[16];
#pragma unroll
            for (int i = 0; i < 16; ++i) acc[i] = 0.f;
            mm4x4g<false>(g_pooled + rr0*VISD,       VISD, W_obs + c0*VISD,       VISD, lane, acc);
            mm4x4g<false>(g_pooled + rr0*VISD + 512, VISD, W_obs + c0*VISD + 512, VISD, lane, acc);
            reduceN<16>(acc);
            if (lane == 0)
#pragma unroll
                for (int i = 0; i < 16; ++i)
                    g_obs_enc[(rr0+(i>>2))*FFD + c0+(i&3)] = acc[i] + b_obs[c0+(i&3)];
        }
        for (int i = gtid; i < TN*BN*FFD; i += GRID*TPB) {
            int t = i >> 14, rem = i & 16383, r = rem >> 9, f = rem & 511;
            const float* ap = actions + (r*TN + t)*8;
            const float* wg = W_gi + f*520 + 512;
            float s = b_gi[f];
#pragma unroll
            for (int j = 0; j < 8; ++j) s += ap[j] * wg[j];
            g_act_pre[i] = s;
        }
        for (int i = gtid; i < BN*FFD; i += GRID*TPB)
            g_h[0][i] = init_hidden[i & (FFD-1)];
    }
    gbar(nbar);

    // ===== P3: obs_pre[tau] = obs_enc @ W1o^T + b_post1 ====================
    for (int tau = 0; tau < TN; ++tau) {
        float acc[16];
#pragma unroll
        for (int i = 0; i < 16; ++i) acc[i] = 0.f;
        mm4x4g<false>(g_obs_enc + (r0*TN + tau)*FFD, TN*FFD,
                      W_post1 + c0*1024 + 512, 1024, lane, acc);
        reduceN<16>(acc);
        if (lane == 0)
#pragma unroll
            for (int i = 0; i < 16; ++i)
                g_obs_pre[(tau*BN + r0+(i>>2))*FFD + c0+(i&3)]
                    = acc[i] + b_post1[c0+(i&3)];
    }
    gbar(nbar);

    // ===== P4: s0 = zero-belief posterior ==================================
    {
        float acc[32];
#pragma unroll
        for (int i = 0; i < 32; ++i) acc[i] = 0.f;
        mm4x4s<true>(g_obs_pre + r0*FFD, FFD, sW + 36*128, sofs, lane, acc);
        mm4x4s<true>(g_obs_pre + r0*FFD, FFD, sW + 40*128, sofs, lane, acc+16);
        reduceN<32>(acc);
        if (lane == 0)
#pragma unroll
            for (int i = 0; i < 16; ++i) {
                int r = r0+(i>>2), c = c0+(i&3);
                float mean = acc[i] + b_pm[c];
                float sd   = softplus_f(acc[16+i] + b_ps[c]) + 0.01f;
                float sv   = mean + sd * eps0[r*FFD + c];
                g_s[r*FFD + c] = sv;
                out[r*OSTR + c] = sv;
            }
    }
    gbar(nbar);

    // ===== recurrence ======================================================
    for (int t = 0; t < TN; ++t) {
        float* hr = &g_h[t & 1][0];
        float* hw = &g_h[(t + 1) & 1][0];
        const bool post = (t < TN - 1);

        // S1: gi = relu(s @ W_gis^T + act_pre[t])
        {
            float acc[16];
#pragma unroll
            for (int i = 0; i < 16; ++i) acc[i] = 0.f;
            mm4x4s<false>(g_s + r0*FFD, FFD, sW, sofs, lane, acc);
            reduceN<16>(acc);
            if (lane == 0)
#pragma unroll
                for (int i = 0; i < 16; ++i) {
                    int r = r0+(i>>2), c = c0+(i&3);
                    g_gi[r*FFD + c] =
                        fmaxf(acc[i] + g_act_pre[(t*BN + r)*FFD + c], 0.f);
                }
        }
        gbar(nbar);

        // S2: GRU gates (CTA-local per feature) -> h_new
        {
            float a01[32];
#pragma unroll
            for (int i = 0; i < 32; ++i) a01[i] = 0.f;
            mm4x4s<false>(g_gi + r0*FFD, FFD, sW + 4*128,  sofs, lane, a01);     // x_r
            mm4x4s<false>(hr   + r0*FFD, FFD, sW + 16*128, sofs, lane, a01);     // h_r
            mm4x4s<false>(g_gi + r0*FFD, FFD, sW + 8*128,  sofs, lane, a01+16);  // x_z
            mm4x4s<false>(hr   + r0*FFD, FFD, sW + 20*128, sofs, lane, a01+16);  // h_z
            reduceN<32>(a01);
            float an[32];
#pragma unroll
            for (int i = 0; i < 32; ++i) an[i] = 0.f;
            mm4x4s<false>(g_gi + r0*FFD, FFD, sW + 12*128, sofs, lane, an);      // x_n
            mm4x4s<false>(hr   + r0*FFD, FFD, sW + 24*128, sofs, lane, an+16);   // h_n
            reduceN<32>(an);
            if (lane == 0)
#pragma unroll
                for (int i = 0; i < 16; ++i) {
                    int r = r0+(i>>2), c = c0+(i&3);
                    float rg = sigm_f(a01[i]    + bih[c]     + bhh[c]);
                    float zg = sigm_f(a01[16+i] + bih[FFD+c] + bhh[FFD+c]);
                    float ng = tanh_f(an[i] + bih[2*FFD+c]
                                      + rg*(an[16+i] + bhh[2*FFD+c]));
                    hw[r*FFD + c] = (1.f - zg)*ng + zg*hr[r*FFD + c];
                }
        }
        gbar(nbar);

        // S3: mid = relu(h_new @ W^T + addend)
        {
            float acc[16];
#pragma unroll
            for (int i = 0; i < 16; ++i) acc[i] = 0.f;
            mm4x4s<false>(hw + r0*FFD, FFD, sW + (post?28:32)*128, sofs, lane, acc);
            reduceN<16>(acc);
            if (lane == 0)
#pragma unroll
                for (int i = 0; i < 16; ++i) {
                    int r = r0+(i>>2), c = c0+(i&3);
                    float add = post ? g_obs_pre[((t+1)*BN + r)*FFD + c] : b_pr1[c];
                    g_mid[r*FFD + c] = fmaxf(acc[i] + add, 0.f);
                }
        }
        gbar(nbar);

        // S4: s = mean + (softplus(stdpre)+0.01)*eps -> out[:,t+1,:]
        {
            const float* bm = post ? b_pm : b_prm;
            const float* bs = post ? b_ps : b_prs;
            float acc[32];
#pragma unroll
            for (int i = 0; i < 32; ++i) acc[i] = 0.f;
            mm4x4s<false>(g_mid + r0*FFD, FFD, sW + (post?36:44)*128, sofs, lane, acc);
            mm4x4s<false>(g_mid + r0*FFD, FFD, sW + (post?40:48)*128, sofs, lane, acc+16);
            reduceN<32>(acc);
            if (lane == 0)
#pragma unroll
                for (int i = 0; i < 16; ++i) {
                    int r = r0+(i>>2), c = c0+(i&3);
                    float mean = acc[i] + bm[c];
                    float sd   = softplus_f(acc[16+i] + bs[c]) + 0.01f;
                    float sv   = mean + sd * eps_seq[(t*BN + r)*FFD + c];
                    g_s[r*FFD + c] = sv;
                    out[r*OSTR + (t+1)*FFD + c] = sv;
                }
        }
        gbar(nbar);
    }
}

extern "C" void kernel_launch(void* const* d_in, const int* in_sizes, int n_in,
                              void* d_out, int out_size) {
    const float* img_feat    = (const float*)d_in[0];
    const float* actions     = (const float*)d_in[1];
    const float* eps0        = (const float*)d_in[2];
    const float* eps_seq     = (const float*)d_in[3];
    const float* init_hidden = (const float*)d_in[4];
    const float* W_obs   = (const float*)d_in[5];
    const float* b_obs   = (const float*)d_in[6];
    const float* W_post1 = (const float*)d_in[7];
    const float* b_post1 = (const float*)d_in[8];
    const float* W_pm    = (const float*)d_in[9];
    const float* b_pm    = (const float*)d_in[10];
    const float* W_ps    = (const float*)d_in[11];
    const float* b_ps    = (const float*)d_in[12];
    const float* W_gi    = (const float*)d_in[13];
    const float* b_gi    = (const float*)d_in[14];
    const float* Wih     = (const float*)d_in[15];
    const float* Whh     = (const float*)d_in[16];
    const float* bih     = (const float*)d_in[17];
    const float* bhh     = (const float*)d_in[18];
    const float* W_pr1   = (const float*)d_in[19];
    const float* b_pr1   = (const float*)d_in[20];
    const float* W_prm   = (const float*)d_in[21];
    const float* b_prm   = (const float*)d_in[22];
    const float* W_prs   = (const float*)d_in[23];
    const float* b_prs   = (const float*)d_in[24];
    float* out = (float*)d_out;

    cudaFuncSetAttribute(rssm_kernel,
                         cudaFuncAttributeMaxDynamicSharedMemorySize, SMEM_BYTES);
    reset_kernel<<<1, 1>>>();
    rssm_kernel<<<GRID, TPB, SMEM_BYTES>>>(
        img_feat, actions, eps0, eps_seq, init_hidden,
        W_obs, b_obs, W_post1, b_post1, W_pm, b_pm, W_ps, b_ps,
        W_gi, b_gi, Wih, Whh, bih, bhh, W_pr1, b_pr1,
        W_prm, b_prm, W_prs, b_prs, out);
}

// round 14
// speedup vs baseline: 1.0016x; 1.0016x over previous
#include <cuda_runtime.h>

#define GRID 128
#define TPB  512
#define NWP  16
#define BN   32
#define TN   32
#define VISD 1024
#define FFD  512
#define OSTR (33*FFD)
#define NSLOT 52
#define SMEM_BYTES (NSLOT*128*16)

// ---------------- static device scratch (no runtime allocations) -----------
__device__ float g_pooled[BN*TN*VISD];
__device__ float g_obs_enc[BN*TN*FFD];
__device__ float g_obs_pre[TN*BN*FFD];
__device__ float g_act_pre[TN*BN*FFD];
__device__ float g_s[BN*FFD];
__device__ float g_h[2][BN*FFD];
__device__ float g_gi[BN*FFD];
__device__ float g_mid[BN*FFD];
__device__ unsigned g_arrive;

// ---------------- grid barrier (monotonic counter; proven in R12) ----------
__device__ __forceinline__ void gbar(unsigned& nbar) {
    nbar += GRID;
    __threadfence();               // release my stores (CCTL.IVALL)
    __syncthreads();
    if (threadIdx.x == 0) {
        atomicAdd(&g_arrive, 1u);
        while (*(volatile unsigned*)&g_arrive < nbar) { }
        __threadfence();           // acquire: invalidate this SM's L1
    }
    __syncthreads();
}

// ---------------- math -----------------------------------------------------
__device__ __forceinline__ float sigm_f(float x) {
    return __fdividef(1.f, 1.f + __expf(-x));
}
__device__ __forceinline__ float tanh_f(float x) {
    x = fminf(fmaxf(x, -15.f), 15.f);
    float e = __expf(2.f * x);
    return (e - 1.f) * __fdividef(1.f, e + 1.f);
}
__device__ __forceinline__ float softplus_f(float x) {
    return fmaxf(x, 0.f) + __logf(1.f + __expf(-fabsf(x)));
}

// ---------------- warp GEMM tiles: 2 rows x 4 cols, lanes along K=512 ------
__device__ __forceinline__ float dot16(const float4 a[4], const float4 b[4]) {
    float s = 0.f;
#pragma unroll
    for (int j = 0; j < 4; ++j)
        s += a[j].x*b[j].x + a[j].y*b[j].y + a[j].z*b[j].z + a[j].w*b[j].w;
    return s;
}
template<bool RELU>
__device__ __forceinline__ void load_act2(const float* act, int as, int lane,
                                          float4 a[2][4]) {
#pragma unroll
    for (int r = 0; r < 2; ++r) {
        const float4* p = reinterpret_cast<const float4*>(act + r*as) + lane*4;
#pragma unroll
        for (int j = 0; j < 4; ++j) {
            float4 v = p[j];
            if (RELU) { v.x=fmaxf(v.x,0.f); v.y=fmaxf(v.y,0.f);
                        v.z=fmaxf(v.z,0.f); v.w=fmaxf(v.w,0.f); }
            a[r][j] = v;
        }
    }
}
// gmem-weight variant (col stride ws floats)
template<bool RELU>
__device__ __forceinline__ void mm2x4g(const float* act, int as, const float* W,
                                       int ws, int lane, float* acc) {
    float4 a[2][4];
    load_act2<RELU>(act, as, lane, a);
#pragma unroll
    for (int c = 0; c < 4; ++c) {
        float4 wv[4];
        const float4* p = reinterpret_cast<const float4*>(W + c*ws) + lane*4;
#pragma unroll
        for (int j = 0; j < 4; ++j) wv[j] = p[j];
#pragma unroll
        for (int r = 0; r < 2; ++r) acc[r*4+c] += dot16(a[r], wv);
    }
}
// smem-weight variant: 4 consecutive 128-f4 slots, swizzled per-lane offsets
template<bool RELU>
__device__ __forceinline__ void mm2x4s(const float* act, int as, const float4* sWc,
                                       const int sofs[4], int lane, float* acc) {
    float4 a[2][4];
    load_act2<RELU>(act, as, lane, a);
#pragma unroll
    for (int c = 0; c < 4; ++c) {
        float4 wv[4];
#pragma unroll
        for (int j = 0; j < 4; ++j) wv[j] = sWc[c*128 + sofs[j]];
#pragma unroll
        for (int r = 0; r < 2; ++r) acc[r*4+c] += dot16(a[r], wv);
    }
}
template<int N>
__device__ __forceinline__ void reduceN(float* acc) {
#pragma unroll
    for (int off = 16; off > 0; off >>= 1)
#pragma unroll
        for (int i = 0; i < N; ++i)
            acc[i] += __shfl_xor_sync(0xFFFFFFFFu, acc[i], off);
}

// ---------------------------------------------------------------------------
__global__ void reset_kernel() { g_arrive = 0; }

__global__ void __launch_bounds__(TPB, 1)
rssm_kernel(const float* __restrict__ img_feat, const float* __restrict__ actions,
            const float* __restrict__ eps0,     const float* __restrict__ eps_seq,
            const float* __restrict__ init_hidden,
            const float* __restrict__ W_obs,   const float* __restrict__ b_obs,
            const float* __restrict__ W_post1, const float* __restrict__ b_post1,
            const float* __restrict__ W_pm,    const float* __restrict__ b_pm,
            const float* __restrict__ W_ps,    const float* __restrict__ b_ps,
            const float* __restrict__ W_gi,    const float* __restrict__ b_gi,
            const float* __restrict__ Wih,     const float* __restrict__ Whh,
            const float* __restrict__ bih,     const float* __restrict__ bhh,
            const float* __restrict__ W_pr1,   const float* __restrict__ b_pr1,
            const float* __restrict__ W_prm,   const float* __restrict__ b_prm,
            const float* __restrict__ W_prs,   const float* __restrict__ b_prs,
            float* __restrict__ out)
{
    extern __shared__ float4 sW[];           // 52 slots x 128 float4 (swizzled)
    const int tid  = threadIdx.x;
    const int cta  = blockIdx.x;
    const int lane = tid & 31;
    const int w    = tid >> 5;
    const int gtid = cta * TPB + tid;
    const int r0   = 2 * w;                  // warp's 2 batch rows (16w x 2 = 32)
    const int c0   = cta * 4;                // CTA's 4 feature columns
    unsigned nbar = 0;

    int sofs[4];                             // per-lane swizzled f4 offsets
#pragma unroll
    for (int j = 0; j < 4; ++j) { int ix = 4*lane + j; sofs[j] = ix ^ ((ix>>3)&7); }

    // ===== stage this CTA's scan weights into swizzled SMEM ================
    {
        const float* src[NSLOT];
#pragma unroll
        for (int j = 0; j < 4; ++j) {
            src[0+j]  = W_gi + (c0+j)*520;                       // state half
#pragma unroll
            for (int g = 0; g < 3; ++g) {
                src[4+g*4+j]  = Wih + (g*FFD + c0 + j)*FFD;
                src[16+g*4+j] = Whh + (g*FFD + c0 + j)*FFD;
            }
            src[28+j] = W_post1 + (c0+j)*1024;                   // belief half
            src[32+j] = W_pr1 + (c0+j)*FFD;
            src[36+j] = W_pm  + (c0+j)*FFD;
            src[40+j] = W_ps  + (c0+j)*FFD;
            src[44+j] = W_prm + (c0+j)*FFD;
            src[48+j] = W_prs + (c0+j)*FFD;
        }
        for (int i = tid; i < NSLOT*128; i += TPB) {
            int s = i >> 7, k = i & 127;
            sW[s*128 + (k ^ ((k>>3)&7))] =
                reinterpret_cast<const float4*>(src[s])[k];
        }
    }
    __syncthreads();

    // ===== P1: spatial mean pool over 48 floats per (b,t,v) ================
    {
        const int q = lane & 3, o = lane >> 2;
        const int warp_id = cta * NWP + w;
        const float4* base = reinterpret_cast<const float4*>(img_feat);
#pragma unroll 2
        for (int it = 0; it < 64; ++it) {
            int ob = (it * (GRID*NWP) + warp_id) * 8;
            const float4* srcp = base + (long)ob * 12;
            int fi = 12*o + q;
            float4 v0 = srcp[fi], v1 = srcp[fi+4], v2 = srcp[fi+8];
            float s = (v0.x+v0.y)+(v0.z+v0.w)+(v1.x+v1.y)+(v1.z+v1.w)
                    + (v2.x+v2.y)+(v2.z+v2.w);
            s += __shfl_xor_sync(0xFFFFFFFFu, s, 1);
            s += __shfl_xor_sync(0xFFFFFFFFu, s, 2);
            if (q == 0) g_pooled[ob + o] = s * (1.f/48.f);
        }
    }
    gbar(nbar);

    // ===== P2: obs_enc = pooled @ W_obs^T + b_obs ; act_pre ; h0 ===========
    {
        for (int rg = w; rg < 512; rg += NWP) {
            int rr0 = rg * 2;
            float acc[8];
#pragma unroll
            for (int i = 0; i < 8; ++i) acc[i] = 0.f;
            mm2x4g<false>(g_pooled + rr0*VISD,       VISD, W_obs + c0*VISD,       VISD, lane, acc);
            mm2x4g<false>(g_pooled + rr0*VISD + 512, VISD, W_obs + c0*VISD + 512, VISD, lane, acc);
            reduceN<8>(acc);
            if (lane == 0)
#pragma unroll
                for (int i = 0; i < 8; ++i)
                    g_obs_enc[(rr0+(i>>2))*FFD + c0+(i&3)] = acc[i] + b_obs[c0+(i&3)];
        }
        for (int i = gtid; i < TN*BN*FFD; i += GRID*TPB) {
            int t = i >> 14, rem = i & 16383, r = rem >> 9, fc = rem & 511;
            const float* ap = actions + (r*TN + t)*8;
            const float* wg = W_gi + fc*520 + 512;
            float s = b_gi[fc];
#pragma unroll
            for (int j = 0; j < 8; ++j) s += ap[j] * wg[j];
            g_act_pre[i] = s;
        }
        for (int i = gtid; i < BN*FFD; i += GRID*TPB)
            g_h[0][i] = init_hidden[i & (FFD-1)];
    }
    gbar(nbar);

    // ===== P3: obs_pre[tau] = obs_enc @ W1o^T + b_post1 ====================
    for (int tau = 0; tau < TN; ++tau) {
        float acc[8];
#pragma unroll
        for (int i = 0; i < 8; ++i) acc[i] = 0.f;
        mm2x4g<false>(g_obs_enc + (r0*TN + tau)*FFD, TN*FFD,
                      W_post1 + c0*1024 + 512, 1024, lane, acc);
        reduceN<8>(acc);
        if (lane == 0)
#pragma unroll
            for (int i = 0; i < 8; ++i)
                g_obs_pre[(tau*BN + r0+(i>>2))*FFD + c0+(i&3)]
                    = acc[i] + b_post1[c0+(i&3)];
    }
    gbar(nbar);

    // ===== P4: s0 = zero-belief posterior ==================================
    {
        float acc[16];
#pragma unroll
        for (int i = 0; i < 16; ++i) acc[i] = 0.f;
        mm2x4s<true>(g_obs_pre + r0*FFD, FFD, sW + 36*128, sofs, lane, acc);
        mm2x4s<true>(g_obs_pre + r0*FFD, FFD, sW + 40*128, sofs, lane, acc+8);
        reduceN<16>(acc);
        if (lane == 0)
#pragma unroll
            for (int i = 0; i < 8; ++i) {
                int r = r0+(i>>2), c = c0+(i&3);
                float mean = acc[i] + b_pm[c];
                float sd   = softplus_f(acc[8+i] + b_ps[c]) + 0.01f;
                float sv   = mean + sd * eps0[r*FFD + c];
                g_s[r*FFD + c] = sv;
                out[r*OSTR + c] = sv;
            }
    }
    gbar(nbar);

    // ===== recurrence ======================================================
    for (int t = 0; t < TN; ++t) {
        float* hr = &g_h[t & 1][0];
        float* hw = &g_h[(t + 1) & 1][0];
        const bool post = (t < TN - 1);

        // S1: gi = relu(s @ W_gis^T + act_pre[t])
        {
            float acc[8];
#pragma unroll
            for (int i = 0; i < 8; ++i) acc[i] = 0.f;
            mm2x4s<false>(g_s + r0*FFD, FFD, sW, sofs, lane, acc);
            reduceN<8>(acc);
            if (lane == 0)
#pragma unroll
                for (int i = 0; i < 8; ++i) {
                    int r = r0+(i>>2), c = c0+(i&3);
                    g_gi[r*FFD + c] =
                        fmaxf(acc[i] + g_act_pre[(t*BN + r)*FFD + c], 0.f);
                }
        }
        gbar(nbar);

        // S2: GRU gates (CTA-local per feature) -> h_new
        {
            float rz[16];
#pragma unroll
            for (int i = 0; i < 16; ++i) rz[i] = 0.f;
            mm2x4s<false>(g_gi + r0*FFD, FFD, sW + 4*128,  sofs, lane, rz);     // x_r
            mm2x4s<false>(hr   + r0*FFD, FFD, sW + 16*128, sofs, lane, rz);     // h_r
            mm2x4s<false>(g_gi + r0*FFD, FFD, sW + 8*128,  sofs, lane, rz+8);   // x_z
            mm2x4s<false>(hr   + r0*FFD, FFD, sW + 20*128, sofs, lane, rz+8);   // h_z
            reduceN<16>(rz);
            float nn[16];
#pragma unroll
            for (int i = 0; i < 16; ++i) nn[i] = 0.f;
            mm2x4s<false>(g_gi + r0*FFD, FFD, sW + 12*128, sofs, lane, nn);     // x_n
            mm2x4s<false>(hr   + r0*FFD, FFD, sW + 24*128, sofs, lane, nn+8);   // h_n
            reduceN<16>(nn);
            if (lane == 0)
#pragma unroll
                for (int i = 0; i < 8; ++i) {
                    int r = r0+(i>>2), c = c0+(i&3);
                    float rg = sigm_f(rz[i]    + bih[c]     + bhh[c]);
                    float zg = sigm_f(rz[8+i]  + bih[FFD+c] + bhh[FFD+c]);
                    float ng = tanh_f(nn[i] + bih[2*FFD+c]
                                      + rg*(nn[8+i] + bhh[2*FFD+c]));
                    hw[r*FFD + c] = (1.f - zg)*ng + zg*hr[r*FFD + c];
                }
        }
        gbar(nbar);

        // S3: mid = relu(h_new @ W^T + addend)
        {
            float acc[8];
#pragma unroll
            for (int i = 0; i < 8; ++i) acc[i] = 0.f;
            mm2x4s<false>(hw + r0*FFD, FFD, sW + (post?28:32)*128, sofs, lane, acc);
            reduceN<8>(acc);
            if (lane == 0)
#pragma unroll
                for (int i = 0; i < 8; ++i) {
                    int r = r0+(i>>2), c = c0+(i&3);
                    float add = post ? g_obs_pre[((t+1)*BN + r)*FFD + c] : b_pr1[c];
                    g_mid[r*FFD + c] = fmaxf(acc[i] + add, 0.f);
                }
        }
        gbar(nbar);

        // S4: s = mean + (softplus(stdpre)+0.01)*eps -> out[:,t+1,:]
        {
            const float* bm = post ? b_pm : b_prm;
            const float* bs = post ? b_ps : b_prs;
            float acc[16];
#pragma unroll
            for (int i = 0; i < 16; ++i) acc[i] = 0.f;
            mm2x4s<false>(g_mid + r0*FFD, FFD, sW + (post?36:44)*128, sofs, lane, acc);
            mm2x4s<false>(g_mid + r0*FFD, FFD, sW + (post?40:48)*128, sofs, lane, acc+8);
            reduceN<16>(acc);
            if (lane == 0)
#pragma unroll
                for (int i = 0; i < 8; ++i) {
                    int r = r0+(i>>2), c = c0+(i&3);
                    float mean = acc[i] + bm[c];
                    float sd   = softplus_f(acc[8+i] + bs[c]) + 0.01f;
                    float sv   = mean + sd * eps_seq[(t*BN + r)*FFD + c];
                    g_s[r*FFD + c] = sv;
                    out[r*OSTR + (t+1)*FFD + c] = sv;
                }
        }
        gbar(nbar);
    }
}

extern "C" void kernel_launch(void* const* d_in, const int* in_sizes, int n_in,
                              void* d_out, int out_size) {
    const float* img_feat    = (const float*)d_in[0];
    const float* actions     = (const float*)d_in[1];
    const float* eps0        = (const float*)d_in[2];
    const float* eps_seq     = (const float*)d_in[3];
    const float* init_hidden = (const float*)d_in[4];
    const float* W_obs   = (const float*)d_in[5];
    const float* b_obs   = (const float*)d_in[6];
    const float* W_post1 = (const float*)d_in[7];
    const float* b_post1 = (const float*)d_in[8];
    const float* W_pm    = (const float*)d_in[9];
    const float* b_pm    = (const float*)d_in[10];
    const float* W_ps    = (const float*)d_in[11];
    const float* b_ps    = (const float*)d_in[12];
    const float* W_gi    = (const float*)d_in[13];
    const float* b_gi    = (const float*)d_in[14];
    const float* Wih     = (const float*)d_in[15];
    const float* Whh     = (const float*)d_in[16];
    const float* bih     = (const float*)d_in[17];
    const float* bhh     = (const float*)d_in[18];
    const float* W_pr1   = (const float*)d_in[19];
    const float* b_pr1   = (const float*)d_in[20];
    const float* W_prm   = (const float*)d_in[21];
    const float* b_prm   = (const float*)d_in[22];
    const float* W_prs   = (const float*)d_in[23];
    const float* b_prs   = (const float*)d_in[24];
    float* out = (float*)d_out;

    cudaFuncSetAttribute(rssm_kernel,
                         cudaFuncAttributeMaxDynamicSharedMemorySize, SMEM_BYTES);
    reset_kernel<<<1, 1>>>();
    rssm_kernel<<<GRID, TPB, SMEM_BYTES>>>(
        img_feat, actions, eps0, eps_seq, init_hidden,
        W_obs, b_obs, W_post1, b_post1, W_pm, b_pm, W_ps, b_ps,
        W_gi, b_gi, Wih, Whh, bih, bhh, W_pr1, b_pr1,
        W_prm, b_prm, W_prs, b_prs, out);
}

// round 15
// speedup vs baseline: 1.0550x; 1.0534x over previous
#include <cuda_runtime.h>

#define GRID 128
#define TPB  512
#define NWP  16
#define BN   32
#define TN   32
#define VISD 1024
#define FFD  512
#define OSTR (33*FFD)
#define NSLOT 52
#define SMEM_BYTES (NSLOT*128*16)

// ---------------- static device scratch (no runtime allocations) -----------
__device__ float g_pooled[BN*TN*VISD];
__device__ float g_obs_enc[BN*TN*FFD];
__device__ float g_obs_pre[TN*BN*FFD];
__device__ float g_act_pre[TN*BN*FFD];
__device__ float g_s[BN*FFD];
__device__ float g_h[2][BN*FFD];
__device__ float g_gi[BN*FFD];
__device__ float g_mid[BN*FFD];
__device__ unsigned g_arrive;

// ---------------- grid barrier: CG grid.sync protocol ----------------------
// __syncthreads makes all CTA stores visible to thread 0 (cta scope); the
// red.release.gpu then releases them GPU-wide (cumulativity). The spin's
// ld.acquire.gpu invalidates this SM's L1, so post-barrier normal loads by
// all warps observe other CTAs' stores. This is the libcu++/cooperative
// groups implementation — one release atomic + acquire poll per CTA.
__device__ __forceinline__ void gbar(unsigned& nbar) {
    nbar += GRID;
    __syncthreads();
    if (threadIdx.x == 0) {
        asm volatile("red.release.gpu.global.add.u32 [%0], 1;"
                     :: "l"(&g_arrive) : "memory");
        unsigned x;
        do {
            asm volatile("ld.acquire.gpu.global.u32 %0, [%1];"
                         : "=r"(x) : "l"(&g_arrive) : "memory");
        } while (x < nbar);
    }
    __syncthreads();
}

// ---------------- math -----------------------------------------------------
__device__ __forceinline__ float sigm_f(float x) {
    return __fdividef(1.f, 1.f + __expf(-x));
}
__device__ __forceinline__ float tanh_f(float x) {
    x = fminf(fmaxf(x, -15.f), 15.f);
    float e = __expf(2.f * x);
    return (e - 1.f) * __fdividef(1.f, e + 1.f);
}
__device__ __forceinline__ float softplus_f(float x) {
    return fmaxf(x, 0.f) + __logf(1.f + __expf(-fabsf(x)));
}

// ---------------- warp GEMM tiles: 2 rows x 4 cols, lanes along K=512 ------
__device__ __forceinline__ float dot16(const float4 a[4], const float4 b[4]) {
    float s = 0.f;
#pragma unroll
    for (int j = 0; j < 4; ++j)
        s += a[j].x*b[j].x + a[j].y*b[j].y + a[j].z*b[j].z + a[j].w*b[j].w;
    return s;
}
template<bool RELU>
__device__ __forceinline__ void load_act2(const float* act, int as, int lane,
                                          float4 a[2][4]) {
#pragma unroll
    for (int r = 0; r < 2; ++r) {
        const float4* p = reinterpret_cast<const float4*>(act + r*as) + lane*4;
#pragma unroll
        for (int j = 0; j < 4; ++j) {
            float4 v = p[j];
            if (RELU) { v.x=fmaxf(v.x,0.f); v.y=fmaxf(v.y,0.f);
                        v.z=fmaxf(v.z,0.f); v.w=fmaxf(v.w,0.f); }
            a[r][j] = v;
        }
    }
}
// gmem-weight variant (col stride ws floats)
template<bool RELU>
__device__ __forceinline__ void mm2x4g(const float* act, int as, const float* W,
                                       int ws, int lane, float* acc) {
    float4 a[2][4];
    load_act2<RELU>(act, as, lane, a);
#pragma unroll
    for (int c = 0; c < 4; ++c) {
        float4 wv[4];
        const float4* p = reinterpret_cast<const float4*>(W + c*ws) + lane*4;
#pragma unroll
        for (int j = 0; j < 4; ++j) wv[j] = p[j];
#pragma unroll
        for (int r = 0; r < 2; ++r) acc[r*4+c] += dot16(a[r], wv);
    }
}
// smem-weight variant: 4 consecutive 128-f4 slots, swizzled per-lane offsets
template<bool RELU>
__device__ __forceinline__ void mm2x4s(const float* act, int as, const float4* sWc,
                                       const int sofs[4], int lane, float* acc) {
    float4 a[2][4];
    load_act2<RELU>(act, as, lane, a);
#pragma unroll
    for (int c = 0; c < 4; ++c) {
        float4 wv[4];
#pragma unroll
        for (int j = 0; j < 4; ++j) wv[j] = sWc[c*128 + sofs[j]];
#pragma unroll
        for (int r = 0; r < 2; ++r) acc[r*4+c] += dot16(a[r], wv);
    }
}
template<int N>
__device__ __forceinline__ void reduceN(float* acc) {
#pragma unroll
    for (int off = 16; off > 0; off >>= 1)
#pragma unroll
        for (int i = 0; i < N; ++i)
            acc[i] += __shfl_xor_sync(0xFFFFFFFFu, acc[i], off);
}

// ---------------------------------------------------------------------------
__global__ void reset_kernel() { g_arrive = 0; }

__global__ void __launch_bounds__(TPB, 1)
rssm_kernel(const float* __restrict__ img_feat, const float* __restrict__ actions,
            const float* __restrict__ eps0,     const float* __restrict__ eps_seq,
            const float* __restrict__ init_hidden,
            const float* __restrict__ W_obs,   const float* __restrict__ b_obs,
            const float* __restrict__ W_post1, const float* __restrict__ b_post1,
            const float* __restrict__ W_pm,    const float* __restrict__ b_pm,
            const float* __restrict__ W_ps,    const float* __restrict__ b_ps,
            const float* __restrict__ W_gi,    const float* __restrict__ b_gi,
            const float* __restrict__ Wih,     const float* __restrict__ Whh,
            const float* __restrict__ bih,     const float* __restrict__ bhh,
            const float* __restrict__ W_pr1,   const float* __restrict__ b_pr1,
            const float* __restrict__ W_prm,   const float* __restrict__ b_prm,
            const float* __restrict__ W_prs,   const float* __restrict__ b_prs,
            float* __restrict__ out)
{
    extern __shared__ float4 sW[];           // 52 slots x 128 float4 (swizzled)
    const int tid  = threadIdx.x;
    const int cta  = blockIdx.x;
    const int lane = tid & 31;
    const int w    = tid >> 5;
    const int gtid = cta * TPB + tid;
    const int r0   = 2 * w;                  // warp's 2 batch rows (16w x 2 = 32)
    const int c0   = cta * 4;                // CTA's 4 feature columns
    unsigned nbar = 0;

    int sofs[4];                             // per-lane swizzled f4 offsets
#pragma unroll
    for (int j = 0; j < 4; ++j) { int ix = 4*lane + j; sofs[j] = ix ^ ((ix>>3)&7); }

    // ===== stage this CTA's scan weights into swizzled SMEM ================
    {
        const float* src[NSLOT];
#pragma unroll
        for (int j = 0; j < 4; ++j) {
            src[0+j]  = W_gi + (c0+j)*520;                       // state half
#pragma unroll
            for (int g = 0; g < 3; ++g) {
                src[4+g*4+j]  = Wih + (g*FFD + c0 + j)*FFD;
                src[16+g*4+j] = Whh + (g*FFD + c0 + j)*FFD;
            }
            src[28+j] = W_post1 + (c0+j)*1024;                   // belief half
            src[32+j] = W_pr1 + (c0+j)*FFD;
            src[36+j] = W_pm  + (c0+j)*FFD;
            src[40+j] = W_ps  + (c0+j)*FFD;
            src[44+j] = W_prm + (c0+j)*FFD;
            src[48+j] = W_prs + (c0+j)*FFD;
        }
        for (int i = tid; i < NSLOT*128; i += TPB) {
            int s = i >> 7, k = i & 127;
            sW[s*128 + (k ^ ((k>>3)&7))] =
                reinterpret_cast<const float4*>(src[s])[k];
        }
    }
    __syncthreads();

    // ===== P1: spatial mean pool over 48 floats per (b,t,v) ================
    {
        const int q = lane & 3, o = lane >> 2;
        const int warp_id = cta * NWP + w;
        const float4* base = reinterpret_cast<const float4*>(img_feat);
#pragma unroll 2
        for (int it = 0; it < 64; ++it) {
            int ob = (it * (GRID*NWP) + warp_id) * 8;
            const float4* srcp = base + (long)ob * 12;
            int fi = 12*o + q;
            float4 v0 = srcp[fi], v1 = srcp[fi+4], v2 = srcp[fi+8];
            float s = (v0.x+v0.y)+(v0.z+v0.w)+(v1.x+v1.y)+(v1.z+v1.w)
                    + (v2.x+v2.y)+(v2.z+v2.w);
            s += __shfl_xor_sync(0xFFFFFFFFu, s, 1);
            s += __shfl_xor_sync(0xFFFFFFFFu, s, 2);
            if (q == 0) g_pooled[ob + o] = s * (1.f/48.f);
        }
    }
    gbar(nbar);

    // ===== P2: obs_enc = pooled @ W_obs^T + b_obs ; act_pre ; h0 ===========
    {
        for (int rg = w; rg < 512; rg += NWP) {
            int rr0 = rg * 2;
            float acc[8];
#pragma unroll
            for (int i = 0; i < 8; ++i) acc[i] = 0.f;
            mm2x4g<false>(g_pooled + rr0*VISD,       VISD, W_obs + c0*VISD,       VISD, lane, acc);
            mm2x4g<false>(g_pooled + rr0*VISD + 512, VISD, W_obs + c0*VISD + 512, VISD, lane, acc);
            reduceN<8>(acc);
            if (lane == 0)
#pragma unroll
                for (int i = 0; i < 8; ++i)
                    g_obs_enc[(rr0+(i>>2))*FFD + c0+(i&3)] = acc[i] + b_obs[c0+(i&3)];
        }
        for (int i = gtid; i < TN*BN*FFD; i += GRID*TPB) {
            int t = i >> 14, rem = i & 16383, r = rem >> 9, fc = rem & 511;
            const float* ap = actions + (r*TN + t)*8;
            const float* wg = W_gi + fc*520 + 512;
            float s = b_gi[fc];
#pragma unroll
            for (int j = 0; j < 8; ++j) s += ap[j] * wg[j];
            g_act_pre[i] = s;
        }
        for (int i = gtid; i < BN*FFD; i += GRID*TPB)
            g_h[0][i] = init_hidden[i & (FFD-1)];
    }
    gbar(nbar);

    // ===== P3: obs_pre[tau] = obs_enc @ W1o^T + b_post1 ====================
    for (int tau = 0; tau < TN; ++tau) {
        float acc[8];
#pragma unroll
        for (int i = 0; i < 8; ++i) acc[i] = 0.f;
        mm2x4g<false>(g_obs_enc + (r0*TN + tau)*FFD, TN*FFD,
                      W_post1 + c0*1024 + 512, 1024, lane, acc);
        reduceN<8>(acc);
        if (lane == 0)
#pragma unroll
            for (int i = 0; i < 8; ++i)
                g_obs_pre[(tau*BN + r0+(i>>2))*FFD + c0+(i&3)]
                    = acc[i] + b_post1[c0+(i&3)];
    }
    gbar(nbar);

    // ===== P4: s0 = zero-belief posterior ==================================
    {
        float acc[16];
#pragma unroll
        for (int i = 0; i < 16; ++i) acc[i] = 0.f;
        mm2x4s<true>(g_obs_pre + r0*FFD, FFD, sW + 36*128, sofs, lane, acc);
        mm2x4s<true>(g_obs_pre + r0*FFD, FFD, sW + 40*128, sofs, lane, acc+8);
        reduceN<16>(acc);
        if (lane == 0)
#pragma unroll
            for (int i = 0; i < 8; ++i) {
                int r = r0+(i>>2), c = c0+(i&3);
                float mean = acc[i] + b_pm[c];
                float sd   = softplus_f(acc[8+i] + b_ps[c]) + 0.01f;
                float sv   = mean + sd * eps0[r*FFD + c];
                g_s[r*FFD + c] = sv;
                out[r*OSTR + c] = sv;
            }
    }
    gbar(nbar);

    // ===== recurrence ======================================================
    for (int t = 0; t < TN; ++t) {
        float* hr = &g_h[t & 1][0];
        float* hw = &g_h[(t + 1) & 1][0];
        const bool post = (t < TN - 1);

        // S1: gi = relu(s @ W_gis^T + act_pre[t])
        {
            float acc[8];
#pragma unroll
            for (int i = 0; i < 8; ++i) acc[i] = 0.f;
            mm2x4s<false>(g_s + r0*FFD, FFD, sW, sofs, lane, acc);
            reduceN<8>(acc);
            if (lane == 0)
#pragma unroll
                for (int i = 0; i < 8; ++i) {
                    int r = r0+(i>>2), c = c0+(i&3);
                    g_gi[r*FFD + c] =
                        fmaxf(acc[i] + g_act_pre[(t*BN + r)*FFD + c], 0.f);
                }
        }
        gbar(nbar);

        // S2: GRU gates (CTA-local per feature) -> h_new
        {
            float rz[16];
#pragma unroll
            for (int i = 0; i < 16; ++i) rz[i] = 0.f;
            mm2x4s<false>(g_gi + r0*FFD, FFD, sW + 4*128,  sofs, lane, rz);     // x_r
            mm2x4s<false>(hr   + r0*FFD, FFD, sW + 16*128, sofs, lane, rz);     // h_r
            mm2x4s<false>(g_gi + r0*FFD, FFD, sW + 8*128,  sofs, lane, rz+8);   // x_z
            mm2x4s<false>(hr   + r0*FFD, FFD, sW + 20*128, sofs, lane, rz+8);   // h_z
            reduceN<16>(rz);
            float nn[16];
#pragma unroll
            for (int i = 0; i < 16; ++i) nn[i] = 0.f;
            mm2x4s<false>(g_gi + r0*FFD, FFD, sW + 12*128, sofs, lane, nn);     // x_n
            mm2x4s<false>(hr   + r0*FFD, FFD, sW + 24*128, sofs, lane, nn+8);   // h_n
            reduceN<16>(nn);
            if (lane == 0)
#pragma unroll
                for (int i = 0; i < 8; ++i) {
                    int r = r0+(i>>2), c = c0+(i&3);
                    float rg = sigm_f(rz[i]    + bih[c]     + bhh[c]);
                    float zg = sigm_f(rz[8+i]  + bih[FFD+c] + bhh[FFD+c]);
                    float ng = tanh_f(nn[i] + bih[2*FFD+c]
                                      + rg*(nn[8+i] + bhh[2*FFD+c]));
                    hw[r*FFD + c] = (1.f - zg)*ng + zg*hr[r*FFD + c];
                }
        }
        gbar(nbar);

        // S3: mid = relu(h_new @ W^T + addend)
        {
            float acc[8];
#pragma unroll
            for (int i = 0; i < 8; ++i) acc[i] = 0.f;
            mm2x4s<false>(hw + r0*FFD, FFD, sW + (post?28:32)*128, sofs, lane, acc);
            reduceN<8>(acc);
            if (lane == 0)
#pragma unroll
                for (int i = 0; i < 8; ++i) {
                    int r = r0+(i>>2), c = c0+(i&3);
                    float add = post ? g_obs_pre[((t+1)*BN + r)*FFD + c] : b_pr1[c];
                    g_mid[r*FFD + c] = fmaxf(acc[i] + add, 0.f);
                }
        }
        gbar(nbar);

        // S4: s = mean + (softplus(stdpre)+0.01)*eps -> out[:,t+1,:]
        {
            const float* bm = post ? b_pm : b_prm;
            const float* bs = post ? b_ps : b_prs;
            float acc[16];
#pragma unroll
            for (int i = 0; i < 16; ++i) acc[i] = 0.f;
            mm2x4s<false>(g_mid + r0*FFD, FFD, sW + (post?36:44)*128, sofs, lane, acc);
            mm2x4s<false>(g_mid + r0*FFD, FFD, sW + (post?40:48)*128, sofs, lane, acc+8);
            reduceN<16>(acc);
            if (lane == 0)
#pragma unroll
                for (int i = 0; i < 8; ++i) {
                    int r = r0+(i>>2), c = c0+(i&3);
                    float mean = acc[i] + bm[c];
                    float sd   = softplus_f(acc[8+i] + bs[c]) + 0.01f;
                    float sv   = mean + sd * eps_seq[(t*BN + r)*FFD + c];
                    g_s[r*FFD + c] = sv;
                    out[r*OSTR + (t+1)*FFD + c] = sv;
                }
        }
        if (t + 1 < TN) gbar(nbar);   // no reader after the final S4
    }
}

extern "C" void kernel_launch(void* const* d_in, const int* in_sizes, int n_in,
                              void* d_out, int out_size) {
    const float* img_feat    = (const float*)d_in[0];
    const float* actions     = (const float*)d_in[1];
    const float* eps0        = (const float*)d_in[2];
    const float* eps_seq     = (const float*)d_in[3];
    const float* init_hidden = (const float*)d_in[4];
    const float* W_obs   = (const float*)d_in[5];
    const float* b_obs   = (const float*)d_in[6];
    const float* W_post1 = (const float*)d_in[7];
    const float* b_post1 = (const float*)d_in[8];
    const float* W_pm    = (const float*)d_in[9];
    const float* b_pm    = (const float*)d_in[10];
    const float* W_ps    = (const float*)d_in[11];
    const float* b_ps    = (const float*)d_in[12];
    const float* W_gi    = (const float*)d_in[13];
    const float* b_gi    = (const float*)d_in[14];
    const float* Wih     = (const float*)d_in[15];
    const float* Whh     = (const float*)d_in[16];
    const float* bih     = (const float*)d_in[17];
    const float* bhh     = (const float*)d_in[18];
    const float* W_pr1   = (const float*)d_in[19];
    const float* b_pr1   = (const float*)d_in[20];
    const float* W_prm   = (const float*)d_in[21];
    const float* b_prm   = (const float*)d_in[22];
    const float* W_prs   = (const float*)d_in[23];
    const float* b_prs   = (const float*)d_in[24];
    float* out = (float*)d_out;

    cudaFuncSetAttribute(rssm_kernel,
                         cudaFuncAttributeMaxDynamicSharedMemorySize, SMEM_BYTES);
    reset_kernel<<<1, 1>>>();
    rssm_kernel<<<GRID, TPB, SMEM_BYTES>>>(
        img_feat, actions, eps0, eps_seq, init_hidden,
        W_obs, b_obs, W_post1, b_post1, W_pm, b_pm, W_ps, b_ps,
        W_gi, b_gi, Wih, Whh, bih, bhh, W_pr1, b_pr1,
        W_prm, b_prm, W_prs, b_prs, out);
}